// round 13
// baseline (speedup 1.0000x reference)
#include <cuda_runtime.h>
#include <math.h>

// ---------------------------------------------------------------------------
// ProtICU R12: grid >= 1024 CTAs for conv2/conv3 (z channel-split / finer L
// tiles); fc 16-row tiles + plain-float smem. All hot grids were CTA-count
// capped at <=22% occupancy before.
// ---------------------------------------------------------------------------

#define NB 32
typedef unsigned long long u64;

__device__ float g_h1[NB * 1024 * 128];
__device__ float g_h2[NB * 512 * 128];
__device__ float g_h3[NB * 256 * 128];
__device__ float g_f [NB * 256 * 128];
__device__ float g_fsq[NB * 256];
__device__ float g_w1t[76 * 5 * 128];
__device__ float g_w2t[128 * 5 * 128];
__device__ float g_w3t[128 * 5 * 128];
__device__ float g_wo1t[128 * 128];
__device__ float g_wo2t[128 * 128];
__device__ float g_psq[128];
__device__ float g_minpart[NB * 16 * 128];

__device__ __forceinline__ void ffma2(u64& d, u64 a, u64 b) {
    asm("fma.rn.f32x2 %0, %1, %2, %0;" : "+l"(d) : "l"(a), "l"(b));
}
__device__ __forceinline__ u64 dup2(float v) {
    u64 r;
    asm("mov.b64 %0, {%1, %1};" : "=l"(r) : "f"(v));
    return r;
}

// ---------------------------------------------------------------------------
// Prep: transposed weights.
// ---------------------------------------------------------------------------
__global__ void prep_kernel(const float* __restrict__ W1, const float* __restrict__ W2,
                            const float* __restrict__ W3, const float* __restrict__ Wo1,
                            const float* __restrict__ Wo2, const float* __restrict__ proto) {
    const int stride = gridDim.x * blockDim.x;
    for (int i = blockIdx.x * blockDim.x + threadIdx.x; i < 128 * 5 * 128; i += stride) {
        const int o  = i & 127;
        const int ck = i >> 7;
        const int c = ck / 5, k = ck - 5 * c;
        if (i < 76 * 5 * 128) g_w1t[i] = W1[(o * 76 + c) * 5 + k];
        g_w2t[i] = W2[(o * 128 + c) * 5 + k];
        g_w3t[i] = W3[(o * 128 + c) * 5 + k];
        if (i < 128 * 128) {
            g_wo1t[i] = Wo1[o * 128 + ck];
            g_wo2t[i] = Wo2[o * 128 + ck];
        }
        if (i < 128) {
            float s = 0.f;
            for (int d = 0; d < 128; d++) { float v = proto[i * 128 + d]; s = fmaf(v, v, s); }
            g_psq[i] = s;
        }
    }
}

// ---------------------------------------------------------------------------
// Conv1d(k=5,same)+ReLU+maxpool2 (same template as R7; launches retuned).
// ---------------------------------------------------------------------------
template <int CIN, int NPOS, int NCH>
__global__ void __launch_bounds__(128)
conv_pool_v5(const float* __restrict__ in, const float* __restrict__ wt,
             const float* __restrict__ bias, float* __restrict__ out,
             int Lin, int Lpool) {
    constexpr int TPRE   = NPOS * 4;
    constexpr int XS     = TPRE + 4;
    constexpr int NCHUNK = CIN / 4;
    constexpr int WR     = 64 * NCH;
    constexpr int WCH    = 20 * WR;
    constexpr int WPC    = WCH / 4;
    constexpr int SEGS   = WR / 4;
    extern __shared__ char smem[];
    float* ws = (float*)smem;
    float* xs = (float*)(smem + 2 * WCH * 4);

    const int tid = threadIdx.x;
    const int op  = tid & 31;
    const int q   = tid >> 5;
    const int jb  = q * NPOS;
    const int b   = blockIdx.y;
    const int l0  = blockIdx.x * TPRE;
    const int co0 = (NCH == 2) ? 0 : blockIdx.z * 64;

    const unsigned ws_base = (unsigned)__cvta_generic_to_shared(ws);

    for (int i = tid; i < WPC; i += 128) {
        const int row = i / SEGS, seg = i - row * SEGS;
        const float* src = wt + row * 128 + co0 + seg * 4;
        asm volatile("cp.async.ca.shared.global [%0], [%1], 16;"
                     :: "r"(ws_base + i * 16), "l"(src));
    }
    asm volatile("cp.async.commit_group;" ::: "memory");

    const float* inb = in + (size_t)b * Lin * CIN;
    for (int i = tid; i < XS * CIN; i += 128) {
        const int pos = i / CIN;
        const int c   = i - pos * CIN;
        const int l   = l0 - 2 + pos;
        xs[c * XS + pos] = (l >= 0 && l < Lin) ? inb[(size_t)l * CIN + c] : 0.f;
    }

    u64 accA[NPOS], accB[NPOS];
    {
        const float2 ba = *(const float2*)(bias + co0 + 2 * op);
        u64 pa;
        asm("mov.b64 %0, {%1,%2};" : "=l"(pa) : "f"(ba.x), "f"(ba.y));
#pragma unroll
        for (int j = 0; j < NPOS; j++) accA[j] = pa;
        if (NCH == 2) {
            const float2 bb = *(const float2*)(bias + 64 + 2 * op);
            u64 pb;
            asm("mov.b64 %0, {%1,%2};" : "=l"(pb) : "f"(bb.x), "f"(bb.y));
#pragma unroll
            for (int j = 0; j < NPOS; j++) accB[j] = pb;
        }
    }

    for (int ch = 0; ch < NCHUNK; ch++) {
        asm volatile("cp.async.wait_group 0;" ::: "memory");
        __syncthreads();
        if (ch + 1 < NCHUNK) {
            const float*   srcb = wt + (ch + 1) * 20 * 128;
            const unsigned dst  = ws_base + ((ch + 1) & 1) * WCH * 4;
            for (int i = tid; i < WPC; i += 128) {
                const int row = i / SEGS, seg = i - row * SEGS;
                asm volatile("cp.async.ca.shared.global [%0], [%1], 16;"
                             :: "r"(dst + i * 16), "l"(srcb + row * 128 + co0 + seg * 4));
            }
            asm volatile("cp.async.commit_group;" ::: "memory");
        }
        const float* wbuf = ws + (ch & 1) * WCH;
        const int c0 = ch * 4;
#pragma unroll
        for (int cc = 0; cc < 4; cc++) {
            const float* xc = xs + (c0 + cc) * XS + jb;
            u64 xr[NPOS + 4];
#pragma unroll
            for (int p = 0; p < NPOS + 4; p++) xr[p] = dup2(xc[p]);
#pragma unroll
            for (int k = 0; k < 5; k++) {
                const float* wrow = wbuf + (cc * 5 + k) * WR;
                const u64 wa = *(const u64*)(wrow + 2 * op);
                if (NCH == 2) {
                    const u64 wb = *(const u64*)(wrow + 64 + 2 * op);
#pragma unroll
                    for (int j = 0; j < NPOS; j++) {
                        ffma2(accA[j], wa, xr[j + k]);
                        ffma2(accB[j], wb, xr[j + k]);
                    }
                } else {
#pragma unroll
                    for (int j = 0; j < NPOS; j++) ffma2(accA[j], wa, xr[j + k]);
                }
            }
        }
    }

    float* outb = out + ((size_t)b * Lpool + l0 / 2 + jb / 2) * 128 + co0 + 2 * op;
#pragma unroll
    for (int m = 0; m < NPOS / 2; m++) {
        const float2 a0 = *(const float2*)&accA[2 * m];
        const float2 a1 = *(const float2*)&accA[2 * m + 1];
        float2 ra;
        ra.x = fmaxf(fmaxf(a0.x, a1.x), 0.f);
        ra.y = fmaxf(fmaxf(a0.y, a1.y), 0.f);
        *(float2*)(outb + (size_t)m * 128) = ra;
        if (NCH == 2) {
            const float2 b0 = *(const float2*)&accB[2 * m];
            const float2 b1 = *(const float2*)&accB[2 * m + 1];
            float2 rb;
            rb.x = fmaxf(fmaxf(b0.x, b1.x), 0.f);
            rb.y = fmaxf(fmaxf(b0.y, b1.y), 0.f);
            *(float2*)(outb + (size_t)m * 128 + 64) = rb;
        }
    }
}

// ---------------------------------------------------------------------------
// Fused 1x1 convs (2 layers) + ReLU + fsq, 16-row tiles, plain-float smem.
// 128 threads = 32 channel-pairs (x2 halves) x 4 quarters of 4 rows.
// smem: ws 16384 + hs 8704 + ms 8704 = 33792 B -> grid 512, ~6 CTAs fit.
// ---------------------------------------------------------------------------
__global__ void __launch_bounds__(128)
fc_fused_v2(const float* __restrict__ in, const float* __restrict__ w1t,
            const float* __restrict__ b1, const float* __restrict__ w2t,
            const float* __restrict__ b2, float* __restrict__ f,
            float* __restrict__ fsq) {
    extern __shared__ char smem[];
    float* ws = (float*)smem;                      // 2 x 2048 floats
    float* hs = (float*)(smem + 16384);            // [c*17 + r], 16 rows
    float* ms = (float*)(smem + 16384 + 8704);

    const int tid  = threadIdx.x;
    const int op   = tid & 31;
    const int q    = tid >> 5;
    const int r0   = q * 4;
    const int b    = blockIdx.y;
    const int row0 = blockIdx.x * 16;
    const unsigned ws_base = (unsigned)__cvta_generic_to_shared(ws);

    for (int i = tid; i < 512; i += 128) {
        asm volatile("cp.async.ca.shared.global [%0], [%1], 16;"
                     :: "r"(ws_base + i * 16), "l"(w1t + i * 4));
    }
    asm volatile("cp.async.commit_group;" ::: "memory");

    const float* inb = in + ((size_t)b * 256 + row0) * 128;
    for (int i = tid; i < 16 * 128; i += 128) {
        const int r = i >> 7, c = i & 127;
        hs[c * 17 + r] = inb[i];
    }

    u64 accA[4], accB[4];
    {
        const float2 ba = *(const float2*)(b1 + 2 * op);
        const float2 bb = *(const float2*)(b1 + 64 + 2 * op);
        u64 pa, pb;
        asm("mov.b64 %0, {%1,%2};" : "=l"(pa) : "f"(ba.x), "f"(ba.y));
        asm("mov.b64 %0, {%1,%2};" : "=l"(pb) : "f"(bb.x), "f"(bb.y));
#pragma unroll
        for (int j = 0; j < 4; j++) { accA[j] = pa; accB[j] = pb; }
    }

    // ---- layer 1 ----
    for (int c0 = 0; c0 < 8; c0++) {
        asm volatile("cp.async.wait_group 0;" ::: "memory");
        __syncthreads();
        if (c0 + 1 < 8) {
            const float*   src = w1t + (c0 + 1) * 2048;
            const unsigned dst = ws_base + ((c0 + 1) & 1) * 8192;
            for (int i = tid; i < 512; i += 128) {
                asm volatile("cp.async.ca.shared.global [%0], [%1], 16;"
                             :: "r"(dst + i * 16), "l"(src + i * 4));
            }
            asm volatile("cp.async.commit_group;" ::: "memory");
        }
        const float* wbuf = ws + (c0 & 1) * 2048;
#pragma unroll
        for (int cc = 0; cc < 16; cc++) {
            const u64 wa = *(const u64*)(wbuf + cc * 128 + 2 * op);
            const u64 wb = *(const u64*)(wbuf + cc * 128 + 64 + 2 * op);
            const float* xb = hs + (c0 * 16 + cc) * 17 + r0;
#pragma unroll
            for (int j = 0; j < 4; j++) {
                const u64 x = dup2(xb[j]);
                ffma2(accA[j], wa, x);
                ffma2(accB[j], wb, x);
            }
        }
    }

    __syncthreads();
    for (int i = tid; i < 512; i += 128) {
        asm volatile("cp.async.ca.shared.global [%0], [%1], 16;"
                     :: "r"(ws_base + i * 16), "l"(w2t + i * 4));
    }
    asm volatile("cp.async.commit_group;" ::: "memory");

#pragma unroll
    for (int j = 0; j < 4; j++) {
        float2 a = *(const float2*)&accA[j];
        float2 c = *(const float2*)&accB[j];
        const int r = r0 + j;
        ms[(2 * op)      * 17 + r] = fmaxf(a.x, 0.f);
        ms[(2 * op + 1)  * 17 + r] = fmaxf(a.y, 0.f);
        ms[(64 + 2 * op) * 17 + r] = fmaxf(c.x, 0.f);
        ms[(65 + 2 * op) * 17 + r] = fmaxf(c.y, 0.f);
    }

    {
        const float2 ba = *(const float2*)(b2 + 2 * op);
        const float2 bb = *(const float2*)(b2 + 64 + 2 * op);
        u64 pa, pb;
        asm("mov.b64 %0, {%1,%2};" : "=l"(pa) : "f"(ba.x), "f"(ba.y));
        asm("mov.b64 %0, {%1,%2};" : "=l"(pb) : "f"(bb.x), "f"(bb.y));
#pragma unroll
        for (int j = 0; j < 4; j++) { accA[j] = pa; accB[j] = pb; }
    }

    // ---- layer 2 ----
    for (int c0 = 0; c0 < 8; c0++) {
        asm volatile("cp.async.wait_group 0;" ::: "memory");
        __syncthreads();
        if (c0 + 1 < 8) {
            const float*   src = w2t + (c0 + 1) * 2048;
            const unsigned dst = ws_base + ((c0 + 1) & 1) * 8192;
            for (int i = tid; i < 512; i += 128) {
                asm volatile("cp.async.ca.shared.global [%0], [%1], 16;"
                             :: "r"(dst + i * 16), "l"(src + i * 4));
            }
            asm volatile("cp.async.commit_group;" ::: "memory");
        }
        const float* wbuf = ws + (c0 & 1) * 2048;
#pragma unroll
        for (int cc = 0; cc < 16; cc++) {
            const u64 wa = *(const u64*)(wbuf + cc * 128 + 2 * op);
            const u64 wb = *(const u64*)(wbuf + cc * 128 + 64 + 2 * op);
            const float* xb = ms + (c0 * 16 + cc) * 17 + r0;
#pragma unroll
            for (int j = 0; j < 4; j++) {
                const u64 x = dup2(xb[j]);
                ffma2(accA[j], wa, x);
                ffma2(accB[j], wb, x);
            }
        }
    }

    float* fb = f + ((size_t)b * 256 + row0 + r0) * 128;
#pragma unroll
    for (int j = 0; j < 4; j++) {
        float2 a = *(const float2*)&accA[j];
        float2 c = *(const float2*)&accB[j];
        a.x = fmaxf(a.x, 0.f); a.y = fmaxf(a.y, 0.f);
        c.x = fmaxf(c.x, 0.f); c.y = fmaxf(c.y, 0.f);
        *(float2*)(fb + (size_t)j * 128 + 2 * op)      = a;
        *(float2*)(fb + (size_t)j * 128 + 64 + 2 * op) = c;
        float s = a.x * a.x + a.y * a.y + c.x * c.x + c.y * c.y;
#pragma unroll
        for (int off = 16; off; off >>= 1) s += __shfl_down_sync(0xffffffffu, s, off);
        if (op == 0) fsq[(size_t)b * 256 + row0 + r0 + j] = s;
    }
}

// ---------------------------------------------------------------------------
// Prototype L2 distances, 16-row chunks (grid 16 x NB = 512 CTAs).
// ---------------------------------------------------------------------------
__global__ void __launch_bounds__(128)
dist_v3(const float* __restrict__ proto) {
    extern __shared__ char smem[];
    float* protoS = (float*)smem;                 // [p*130 + d]
    float* fs     = (float*)(smem + 66560);       // [r*128 + d], 8 rows

    const int b = blockIdx.y, chunk = blockIdx.x;
    const int p = threadIdx.x;

    for (int i = p; i < 128 * 128; i += 128) {
        const int pp = i >> 7, d = i & 127;
        protoS[pp * 130 + d] = proto[i];
    }
    const float psqv = g_psq[p];
    const float* fb = g_f   + ((size_t)(b * 256 + chunk * 16)) * 128;
    const float* fq = g_fsq + b * 256 + chunk * 16;
    float best = 3.4e38f;

    for (int l0 = 0; l0 < 16; l0 += 8) {
        __syncthreads();
        for (int i = p; i < 1024; i += 128) fs[i] = fb[(size_t)l0 * 128 + i];
        __syncthreads();

        u64 acc2[8];
#pragma unroll
        for (int r = 0; r < 8; r++) acc2[r] = 0ull;
#pragma unroll
        for (int dc = 0; dc < 4; dc++) {
            u64 ptr_[16];
#pragma unroll
            for (int i = 0; i < 16; i++)
                ptr_[i] = *(const u64*)(protoS + p * 130 + dc * 32 + 2 * i);
#pragma unroll
            for (int r = 0; r < 8; r++) {
                const float* fr = fs + r * 128 + dc * 32;
#pragma unroll
                for (int i = 0; i < 16; i++)
                    ffma2(acc2[r], ptr_[i], *(const u64*)(fr + 2 * i));
            }
        }
#pragma unroll
        for (int r = 0; r < 8; r++) {
            const float2 a = *(const float2*)&acc2[r];
            const float dot = a.x + a.y;
            const float d2 = fq[l0 + r] - 2.f * dot + psqv;
            best = fminf(best, d2);
        }
    }
    g_minpart[(b * 16 + chunk) * 128 + p] = best;
}

// ---------------------------------------------------------------------------
// Final head.  d_out[0:64] = out(32,2); d_out[64:4160] = min_dis(32,128).
// ---------------------------------------------------------------------------
__global__ void final_kernel(const int* __restrict__ classes, float* __restrict__ outp) {
    const int b = blockIdx.x, p = threadIdx.x;
    float m = 3.4e38f;
#pragma unroll
    for (int c = 0; c < 16; c++)
        m = fminf(m, g_minpart[(b * 16 + c) * 128 + p]);
    const float dis = sqrtf(fmaxf(m, 1e-12f));
    const float sim = logf((dis + 1.f) / (dis + 1e-4f));
    outp[64 + b * 128 + p] = dis;

    __shared__ float ss[128];
    ss[p] = sim;
    __syncthreads();
    if (p < 2) {
        float s = 0.f;
        for (int q = 0; q < 128; q++)
            s += ss[q] * ((classes[q] == p) ? 1.f : -0.5f);
        outp[b * 2 + p] = 1.f / (1.f + expf(-s));
    }
}

// ---------------------------------------------------------------------------
extern "C" void kernel_launch(void* const* d_in, const int* in_sizes, int n_in,
                              void* d_out, int out_size) {
    const float* x     = (const float*)d_in[0];
    const float* W1    = (const float*)d_in[1];
    const float* b1    = (const float*)d_in[2];
    const float* W2    = (const float*)d_in[3];
    const float* b2    = (const float*)d_in[4];
    const float* W3    = (const float*)d_in[5];
    const float* b3    = (const float*)d_in[6];
    const float* Wo1   = (const float*)d_in[7];
    const float* bo1   = (const float*)d_in[8];
    const float* Wo2   = (const float*)d_in[9];
    const float* bo2   = (const float*)d_in[10];
    const float* proto = (const float*)d_in[11];
    const int*   cls   = (const int*)d_in[12];
    float* out = (float*)d_out;
    (void)in_sizes; (void)n_in; (void)out_size;

    void *h1, *h2, *h3, *f, *fsq, *w1t, *w2t, *w3t, *wo1t, *wo2t;
    cudaGetSymbolAddress(&h1, g_h1);
    cudaGetSymbolAddress(&h2, g_h2);
    cudaGetSymbolAddress(&h3, g_h3);
    cudaGetSymbolAddress(&f,  g_f);
    cudaGetSymbolAddress(&fsq, g_fsq);
    cudaGetSymbolAddress(&w1t, g_w1t);
    cudaGetSymbolAddress(&w2t, g_w2t);
    cudaGetSymbolAddress(&w3t, g_w3t);
    cudaGetSymbolAddress(&wo1t, g_wo1t);
    cudaGetSymbolAddress(&wo2t, g_wo2t);

    // smem: conv1 <76,16,2>:  2*20*128*4 + 76*68*4  = 41152
    //       conv2 <128,16,1>: 2*20*64*4  + 128*68*4 = 45056
    //       conv3 <128,8,1>:  2*20*64*4  + 128*36*4 = 28672
    const int smem1 = 41152, smem2 = 45056, smem3 = 28672;
    const int smemfc = 16384 + 2 * 8704;              // 33792
    const int smemd  = 66560 + 4096;                  // 70656
    cudaFuncSetAttribute((const void*)conv_pool_v5<76, 16, 2>,  cudaFuncAttributeMaxDynamicSharedMemorySize, smem1);
    cudaFuncSetAttribute((const void*)conv_pool_v5<128, 16, 1>, cudaFuncAttributeMaxDynamicSharedMemorySize, smem2);
    cudaFuncSetAttribute((const void*)conv_pool_v5<128, 8, 1>,  cudaFuncAttributeMaxDynamicSharedMemorySize, smem3);
    cudaFuncSetAttribute((const void*)fc_fused_v2, cudaFuncAttributeMaxDynamicSharedMemorySize, smemfc);
    cudaFuncSetAttribute((const void*)dist_v3,  cudaFuncAttributeMaxDynamicSharedMemorySize, smemd);

    prep_kernel<<<256, 256>>>(W1, W2, W3, Wo1, Wo2, proto);

    conv_pool_v5<76, 16, 2> <<<dim3(32, NB, 1), 128, smem1>>>(x,          (const float*)w1t, b1, (float*)h1, 2048, 1024);
    conv_pool_v5<128, 16, 1><<<dim3(16, NB, 2), 128, smem2>>>((float*)h1, (const float*)w2t, b2, (float*)h2, 1024, 512);
    conv_pool_v5<128, 8, 1> <<<dim3(16, NB, 2), 128, smem3>>>((float*)h2, (const float*)w3t, b3, (float*)h3, 512,  256);

    fc_fused_v2<<<dim3(16, NB), 128, smemfc>>>((const float*)h3, (const float*)wo1t, bo1,
                                               (const float*)wo2t, bo2, (float*)f, (float*)fsq);
    dist_v3<<<dim3(16, NB), 128, smemd>>>(proto);
    final_kernel<<<NB, 128>>>(cls, out);
}

// round 15
// speedup vs baseline: 1.6938x; 1.6938x over previous
#include <cuda_runtime.h>
#include <cuda_bf16.h>
#include <math.h>

// ---------------------------------------------------------------------------
// ProtICU R15: convs on warp-level tensor cores (mma.sync m16n8k16 bf16,
// fp32 acc, hi/lo split x3 products). tcgen05 is unavailable (harness PTX
// targets plain sm_103), but mma.sync/ldmatrix are sm_80+ features.
// Conv-as-shifted-GEMM: one 68-row x tile per CTA serves all 5 taps via
// ldmatrix row offset. Weights pre-baked in A-fragment order (LDG.128).
// fc/dist/final: unchanged FFMA2 kernels.
// ---------------------------------------------------------------------------

#define NB 32
typedef unsigned long long u64;
typedef unsigned int u32;

__device__ float g_h1[NB * 1024 * 128];
__device__ float g_h2[NB * 512 * 128];
__device__ float g_h3[NB * 256 * 128];
__device__ float g_f [NB * 256 * 128];
__device__ float g_fsq[NB * 256];
__device__ uint4 g_af1[12800];    // conv1 A-frags: 5 taps x 5 ks x 2 split x 8 mt x 32 lanes
__device__ uint4 g_af2[20480];    // conv2: 5 x 8 x 2 x 8 x 32
__device__ uint4 g_af3[20480];
__device__ float g_wo1t[128 * 128];
__device__ float g_wo2t[128 * 128];
__device__ float g_psq[128];
__device__ float g_minpart[NB * 16 * 128];

__device__ __forceinline__ void ffma2(u64& d, u64 a, u64 b) {
    asm("fma.rn.f32x2 %0, %1, %2, %0;" : "+l"(d) : "l"(a), "l"(b));
}
__device__ __forceinline__ u64 dup2(float v) {
    u64 r;
    asm("mov.b64 %0, {%1, %1};" : "=l"(r) : "f"(v));
    return r;
}
__device__ __forceinline__ u32 s2u32(const void* p) {
    u32 a;
    asm("{ .reg .u64 t; cvta.to.shared.u64 t, %1; cvt.u32.u64 %0, t; }" : "=r"(a) : "l"(p));
    return a;
}
__device__ __forceinline__ void ldmx4(u32* r, u32 addr) {
    asm volatile("ldmatrix.sync.aligned.m8n8.x4.shared.b16 {%0,%1,%2,%3}, [%4];"
                 : "=r"(r[0]), "=r"(r[1]), "=r"(r[2]), "=r"(r[3]) : "r"(addr));
}
__device__ __forceinline__ void mma16816(float* d, const uint4& a, u32 b0, u32 b1) {
    asm volatile(
        "mma.sync.aligned.m16n8k16.row.col.f32.bf16.bf16.f32 "
        "{%0,%1,%2,%3},{%4,%5,%6,%7},{%8,%9},{%0,%1,%2,%3};"
        : "+f"(d[0]), "+f"(d[1]), "+f"(d[2]), "+f"(d[3])
        : "r"(a.x), "r"(a.y), "r"(a.z), "r"(a.w), "r"(b0), "r"(b1));
}

// ---------------------------------------------------------------------------
// prep: 1x1-conv weight transposes + prototype norms.
// ---------------------------------------------------------------------------
__global__ void prep_kernel(const float* __restrict__ Wo1, const float* __restrict__ Wo2,
                            const float* __restrict__ proto) {
    const int stride = gridDim.x * blockDim.x;
    for (int i = blockIdx.x * blockDim.x + threadIdx.x; i < 128 * 128; i += stride) {
        const int o = i & 127, c = i >> 7;
        g_wo1t[i] = Wo1[o * 128 + c];
        g_wo2t[i] = Wo2[o * 128 + c];
        if (i < 128) {
            float s = 0.f;
            for (int d = 0; d < 128; d++) { float v = proto[i * 128 + d]; s = fmaf(v, v, s); }
            g_psq[i] = s;
        }
    }
}

// ---------------------------------------------------------------------------
// prep: bake conv weights into mma A-fragment order.
// af[u32 i]: reg=i&3, lane=(i>>2)&31, mt=(i>>7)&7, split=(i>>10)&1, t=i>>11
// (t = tap*NKS+ks). A frag (m16k16 row-major): m = mt*16 + (lane>>2) +
// 8*(reg&1); k = ks*16 + (lane&3)*2 + 4*(reg&2) + e.  W layout: [O][CIN][5].
// ---------------------------------------------------------------------------
__global__ void prep_afrag(const float* __restrict__ W, u32* __restrict__ af,
                           int CIN, int NKS) {
    const int total = 5 * NKS * 2 * 8 * 128;
    const int stride = gridDim.x * blockDim.x;
    for (int i = blockIdx.x * blockDim.x + threadIdx.x; i < total; i += stride) {
        const int reg = i & 3, lane = (i >> 2) & 31, mt = (i >> 7) & 7;
        const int split = (i >> 10) & 1, t = i >> 11;
        const int tap = t / NKS, ks = t - tap * NKS;
        const int m  = mt * 16 + (lane >> 2) + (reg & 1) * 8;
        const int k0 = ks * 16 + (lane & 3) * 2 + (reg & 2) * 4;
        unsigned short h[2];
        for (int e = 0; e < 2; e++) {
            const int c = k0 + e;
            const float v = (c < CIN) ? W[(m * CIN + c) * 5 + tap] : 0.f;
            __nv_bfloat16 b = __float2bfloat16(v);
            if (split) b = __float2bfloat16(v - __bfloat162float(b));
            memcpy(&h[e], &b, 2);
        }
        af[i] = ((u32)h[1] << 16) | (u32)h[0];
    }
}

// ---------------------------------------------------------------------------
// Tensor-core conv1d(k=5,same)+bias+ReLU+maxpool2.
// 256 threads = 8 warps; warp = (mband = wid&3 : 32 out-ch) x (nhalf = wid>>2
// : 32 prepool positions). CTA tile: 128 ch x 64 prepool (32 pooled).
// x tile: 68 rows x 256B (hi + lo), XOR-swizzled 16B chunks; tap shift is a
// row offset in the ldmatrix address. 24 mma per (tap, kstep) per warp.
// ---------------------------------------------------------------------------
template <int CIN, int NKS>
__global__ void __launch_bounds__(256)
conv_mma(const float* __restrict__ in, const uint4* __restrict__ af,
         const float* __restrict__ bias, float* __restrict__ out,
         int Lin, int Lpool) {
    __shared__ __align__(16) char xs[2 * 68 * 256];
    const u32 XHI = s2u32(xs);
    const u32 XLO = XHI + 68 * 256;

    const int tid  = threadIdx.x;
    const int wid  = tid >> 5;
    const int lane = tid & 31;
    const int mb   = wid & 3;
    const int nh   = wid >> 2;
    const int b    = blockIdx.y;
    const int l0   = blockIdx.x * 64;

    // zero tiles
    for (int i = tid; i < (2 * 68 * 256) / 16; i += 256)
        ((uint4*)xs)[i] = make_uint4(0, 0, 0, 0);
    __syncthreads();

    // fill x tile (hi/lo bf16, swizzled)
    const float* inb = in + (size_t)b * Lin * CIN;
    for (int idx = tid; idx < 68 * CIN; idx += 256) {
        const int r = idx / CIN, c = idx - r * CIN;
        const int gl = l0 - 2 + r;
        const float v = (gl >= 0 && gl < Lin) ? inb[(size_t)gl * CIN + c] : 0.f;
        const __nv_bfloat16 hi = __float2bfloat16(v);
        const __nv_bfloat16 lo = __float2bfloat16(v - __bfloat162float(hi));
        const int addr = r * 256 + (((c >> 3) ^ (r & 7)) << 4) + (c & 7) * 2;
        *(__nv_bfloat16*)(xs + addr)             = hi;
        *(__nv_bfloat16*)(xs + 68 * 256 + addr)  = lo;
    }
    __syncthreads();

    float d[2][4][4];
#pragma unroll
    for (int mt = 0; mt < 2; mt++)
#pragma unroll
        for (int nt = 0; nt < 4; nt++)
#pragma unroll
            for (int e = 0; e < 4; e++) d[mt][nt][e] = 0.f;

    // ldmatrix lane geometry: matrix = lane>>3 (ntl = bit1, khalf = bit0)
    const int prow = nh * 32 + ((lane >> 4) << 3) + (lane & 7);
    const int khb  = (lane >> 3) & 1;

#pragma unroll 1
    for (int tap = 0; tap < 5; tap++) {
#pragma unroll
        for (int ks = 0; ks < NKS; ks++) {
            const int t = tap * NKS + ks;
            const uint4 AH0 = af[((t * 2 + 0) * 8 + mb * 2 + 0) * 32 + lane];
            const uint4 AH1 = af[((t * 2 + 0) * 8 + mb * 2 + 1) * 32 + lane];
            const uint4 AL0 = af[((t * 2 + 1) * 8 + mb * 2 + 0) * 32 + lane];
            const uint4 AL1 = af[((t * 2 + 1) * 8 + mb * 2 + 1) * 32 + lane];

            u32 bh[8], bl[8];
#pragma unroll
            for (int g = 0; g < 2; g++) {
                const int pos   = prow + g * 16 + tap;
                const int chunk = ks * 2 + khb;
                const u32 off = (u32)(pos * 256 + ((chunk ^ (pos & 7)) << 4));
                ldmx4(bh + 4 * g, XHI + off);
                ldmx4(bl + 4 * g, XLO + off);
            }
#pragma unroll
            for (int nt = 0; nt < 4; nt++) {
                mma16816(d[0][nt], AH0, bh[2 * nt], bh[2 * nt + 1]);
                mma16816(d[1][nt], AH1, bh[2 * nt], bh[2 * nt + 1]);
                mma16816(d[0][nt], AH0, bl[2 * nt], bl[2 * nt + 1]);
                mma16816(d[1][nt], AH1, bl[2 * nt], bl[2 * nt + 1]);
                mma16816(d[0][nt], AL0, bh[2 * nt], bh[2 * nt + 1]);
                mma16816(d[1][nt], AL1, bh[2 * nt], bh[2 * nt + 1]);
            }
        }
    }

    // epilogue: bias + relu + maxpool2 (pool pair = d[.][.]{0,1} / {2,3})
    float* outb = out + ((size_t)b * Lpool + blockIdx.x * 32) * 128;
#pragma unroll
    for (int mt = 0; mt < 2; mt++) {
        const int ch0 = mb * 32 + mt * 16 + (lane >> 2);
        const float bv0 = bias[ch0];
        const float bv8 = bias[ch0 + 8];
#pragma unroll
        for (int nt = 0; nt < 4; nt++) {
            const int p = nh * 16 + nt * 4 + (lane & 3);
            const float v0 = fmaxf(fmaxf(d[mt][nt][0], d[mt][nt][1]) + bv0, 0.f);
            const float v1 = fmaxf(fmaxf(d[mt][nt][2], d[mt][nt][3]) + bv8, 0.f);
            outb[(size_t)p * 128 + ch0]     = v0;
            outb[(size_t)p * 128 + ch0 + 8] = v1;
        }
    }
}

// ---------------------------------------------------------------------------
// Fused 1x1 convs (2 layers) + ReLU + fsq. (unchanged from R12/R13)
// ---------------------------------------------------------------------------
__global__ void __launch_bounds__(128)
fc_fused_v2(const float* __restrict__ in, const float* __restrict__ w1t,
            const float* __restrict__ b1, const float* __restrict__ w2t,
            const float* __restrict__ b2, float* __restrict__ f,
            float* __restrict__ fsq) {
    extern __shared__ char smem[];
    float* ws = (float*)smem;
    float* hs = (float*)(smem + 16384);
    float* ms = (float*)(smem + 16384 + 8704);

    const int tid  = threadIdx.x;
    const int op   = tid & 31;
    const int q    = tid >> 5;
    const int r0   = q * 4;
    const int b    = blockIdx.y;
    const int row0 = blockIdx.x * 16;
    const unsigned ws_base = (unsigned)__cvta_generic_to_shared(ws);

    for (int i = tid; i < 512; i += 128) {
        asm volatile("cp.async.ca.shared.global [%0], [%1], 16;"
                     :: "r"(ws_base + i * 16), "l"(w1t + i * 4));
    }
    asm volatile("cp.async.commit_group;" ::: "memory");

    const float* inb = in + ((size_t)b * 256 + row0) * 128;
    for (int i = tid; i < 16 * 128; i += 128) {
        const int r = i >> 7, c = i & 127;
        hs[c * 17 + r] = inb[i];
    }

    u64 accA[4], accB[4];
    {
        const float2 ba = *(const float2*)(b1 + 2 * op);
        const float2 bb = *(const float2*)(b1 + 64 + 2 * op);
        u64 pa, pb;
        asm("mov.b64 %0, {%1,%2};" : "=l"(pa) : "f"(ba.x), "f"(ba.y));
        asm("mov.b64 %0, {%1,%2};" : "=l"(pb) : "f"(bb.x), "f"(bb.y));
#pragma unroll
        for (int j = 0; j < 4; j++) { accA[j] = pa; accB[j] = pb; }
    }

    for (int c0 = 0; c0 < 8; c0++) {
        asm volatile("cp.async.wait_group 0;" ::: "memory");
        __syncthreads();
        if (c0 + 1 < 8) {
            const float*   src = w1t + (c0 + 1) * 2048;
            const unsigned dst = ws_base + ((c0 + 1) & 1) * 8192;
            for (int i = tid; i < 512; i += 128) {
                asm volatile("cp.async.ca.shared.global [%0], [%1], 16;"
                             :: "r"(dst + i * 16), "l"(src + i * 4));
            }
            asm volatile("cp.async.commit_group;" ::: "memory");
        }
        const float* wbuf = ws + (c0 & 1) * 2048;
#pragma unroll
        for (int cc = 0; cc < 16; cc++) {
            const u64 wa = *(const u64*)(wbuf + cc * 128 + 2 * op);
            const u64 wb = *(const u64*)(wbuf + cc * 128 + 64 + 2 * op);
            const float* xb = hs + (c0 * 16 + cc) * 17 + r0;
#pragma unroll
            for (int j = 0; j < 4; j++) {
                const u64 x = dup2(xb[j]);
                ffma2(accA[j], wa, x);
                ffma2(accB[j], wb, x);
            }
        }
    }

    __syncthreads();
    for (int i = tid; i < 512; i += 128) {
        asm volatile("cp.async.ca.shared.global [%0], [%1], 16;"
                     :: "r"(ws_base + i * 16), "l"(w2t + i * 4));
    }
    asm volatile("cp.async.commit_group;" ::: "memory");

#pragma unroll
    for (int j = 0; j < 4; j++) {
        float2 a = *(const float2*)&accA[j];
        float2 c = *(const float2*)&accB[j];
        const int r = r0 + j;
        ms[(2 * op)      * 17 + r] = fmaxf(a.x, 0.f);
        ms[(2 * op + 1)  * 17 + r] = fmaxf(a.y, 0.f);
        ms[(64 + 2 * op) * 17 + r] = fmaxf(c.x, 0.f);
        ms[(65 + 2 * op) * 17 + r] = fmaxf(c.y, 0.f);
    }

    {
        const float2 ba = *(const float2*)(b2 + 2 * op);
        const float2 bb = *(const float2*)(b2 + 64 + 2 * op);
        u64 pa, pb;
        asm("mov.b64 %0, {%1,%2};" : "=l"(pa) : "f"(ba.x), "f"(ba.y));
        asm("mov.b64 %0, {%1,%2};" : "=l"(pb) : "f"(bb.x), "f"(bb.y));
#pragma unroll
        for (int j = 0; j < 4; j++) { accA[j] = pa; accB[j] = pb; }
    }

    for (int c0 = 0; c0 < 8; c0++) {
        asm volatile("cp.async.wait_group 0;" ::: "memory");
        __syncthreads();
        if (c0 + 1 < 8) {
            const float*   src = w2t + (c0 + 1) * 2048;
            const unsigned dst = ws_base + ((c0 + 1) & 1) * 8192;
            for (int i = tid; i < 512; i += 128) {
                asm volatile("cp.async.ca.shared.global [%0], [%1], 16;"
                             :: "r"(dst + i * 16), "l"(src + i * 4));
            }
            asm volatile("cp.async.commit_group;" ::: "memory");
        }
        const float* wbuf = ws + (c0 & 1) * 2048;
#pragma unroll
        for (int cc = 0; cc < 16; cc++) {
            const u64 wa = *(const u64*)(wbuf + cc * 128 + 2 * op);
            const u64 wb = *(const u64*)(wbuf + cc * 128 + 64 + 2 * op);
            const float* xb = ms + (c0 * 16 + cc) * 17 + r0;
#pragma unroll
            for (int j = 0; j < 4; j++) {
                const u64 x = dup2(xb[j]);
                ffma2(accA[j], wa, x);
                ffma2(accB[j], wb, x);
            }
        }
    }

    float* fb = f + ((size_t)b * 256 + row0 + r0) * 128;
#pragma unroll
    for (int j = 0; j < 4; j++) {
        float2 a = *(const float2*)&accA[j];
        float2 c = *(const float2*)&accB[j];
        a.x = fmaxf(a.x, 0.f); a.y = fmaxf(a.y, 0.f);
        c.x = fmaxf(c.x, 0.f); c.y = fmaxf(c.y, 0.f);
        *(float2*)(fb + (size_t)j * 128 + 2 * op)      = a;
        *(float2*)(fb + (size_t)j * 128 + 64 + 2 * op) = c;
        float s = a.x * a.x + a.y * a.y + c.x * c.x + c.y * c.y;
#pragma unroll
        for (int off = 16; off; off >>= 1) s += __shfl_down_sync(0xffffffffu, s, off);
        if (op == 0) fsq[(size_t)b * 256 + row0 + r0 + j] = s;
    }
}

// ---------------------------------------------------------------------------
// Prototype L2 distances, 16-row chunks. (unchanged)
// ---------------------------------------------------------------------------
__global__ void __launch_bounds__(128)
dist_v3(const float* __restrict__ proto) {
    extern __shared__ char smem[];
    float* protoS = (float*)smem;
    float* fs     = (float*)(smem + 66560);

    const int b = blockIdx.y, chunk = blockIdx.x;
    const int p = threadIdx.x;

    for (int i = p; i < 128 * 128; i += 128) {
        const int pp = i >> 7, d = i & 127;
        protoS[pp * 130 + d] = proto[i];
    }
    const float psqv = g_psq[p];
    const float* fb = g_f   + ((size_t)(b * 256 + chunk * 16)) * 128;
    const float* fq = g_fsq + b * 256 + chunk * 16;
    float best = 3.4e38f;

    for (int l0 = 0; l0 < 16; l0 += 8) {
        __syncthreads();
        for (int i = p; i < 1024; i += 128) fs[i] = fb[(size_t)l0 * 128 + i];
        __syncthreads();

        u64 acc2[8];
#pragma unroll
        for (int r = 0; r < 8; r++) acc2[r] = 0ull;
#pragma unroll
        for (int dc = 0; dc < 4; dc++) {
            u64 ptr_[16];
#pragma unroll
            for (int i = 0; i < 16; i++)
                ptr_[i] = *(const u64*)(protoS + p * 130 + dc * 32 + 2 * i);
#pragma unroll
            for (int r = 0; r < 8; r++) {
                const float* fr = fs + r * 128 + dc * 32;
#pragma unroll
                for (int i = 0; i < 16; i++)
                    ffma2(acc2[r], ptr_[i], *(const u64*)(fr + 2 * i));
            }
        }
#pragma unroll
        for (int r = 0; r < 8; r++) {
            const float2 a = *(const float2*)&acc2[r];
            const float dot = a.x + a.y;
            const float d2 = fq[l0 + r] - 2.f * dot + psqv;
            best = fminf(best, d2);
        }
    }
    g_minpart[(b * 16 + chunk) * 128 + p] = best;
}

// ---------------------------------------------------------------------------
// Final head.  d_out[0:64] = out(32,2); d_out[64:4160] = min_dis(32,128).
// ---------------------------------------------------------------------------
__global__ void final_kernel(const int* __restrict__ classes, float* __restrict__ outp) {
    const int b = blockIdx.x, p = threadIdx.x;
    float m = 3.4e38f;
#pragma unroll
    for (int c = 0; c < 16; c++)
        m = fminf(m, g_minpart[(b * 16 + c) * 128 + p]);
    const float dis = sqrtf(fmaxf(m, 1e-12f));
    const float sim = logf((dis + 1.f) / (dis + 1e-4f));
    outp[64 + b * 128 + p] = dis;

    __shared__ float ss[128];
    ss[p] = sim;
    __syncthreads();
    if (p < 2) {
        float s = 0.f;
        for (int q = 0; q < 128; q++)
            s += ss[q] * ((classes[q] == p) ? 1.f : -0.5f);
        outp[b * 2 + p] = 1.f / (1.f + expf(-s));
    }
}

// ---------------------------------------------------------------------------
extern "C" void kernel_launch(void* const* d_in, const int* in_sizes, int n_in,
                              void* d_out, int out_size) {
    const float* x     = (const float*)d_in[0];
    const float* W1    = (const float*)d_in[1];
    const float* b1    = (const float*)d_in[2];
    const float* W2    = (const float*)d_in[3];
    const float* b2    = (const float*)d_in[4];
    const float* W3    = (const float*)d_in[5];
    const float* b3    = (const float*)d_in[6];
    const float* Wo1   = (const float*)d_in[7];
    const float* bo1   = (const float*)d_in[8];
    const float* Wo2   = (const float*)d_in[9];
    const float* bo2   = (const float*)d_in[10];
    const float* proto = (const float*)d_in[11];
    const int*   cls   = (const int*)d_in[12];
    float* out = (float*)d_out;
    (void)in_sizes; (void)n_in; (void)out_size;

    void *h1, *h2, *h3, *f, *fsq, *af1, *af2, *af3, *wo1t, *wo2t;
    cudaGetSymbolAddress(&h1, g_h1);
    cudaGetSymbolAddress(&h2, g_h2);
    cudaGetSymbolAddress(&h3, g_h3);
    cudaGetSymbolAddress(&f,  g_f);
    cudaGetSymbolAddress(&fsq, g_fsq);
    cudaGetSymbolAddress(&af1, g_af1);
    cudaGetSymbolAddress(&af2, g_af2);
    cudaGetSymbolAddress(&af3, g_af3);
    cudaGetSymbolAddress(&wo1t, g_wo1t);
    cudaGetSymbolAddress(&wo2t, g_wo2t);

    const int smemfc = 16384 + 2 * 8704;              // 33792
    const int smemd  = 66560 + 4096;                  // 70656
    cudaFuncSetAttribute((const void*)fc_fused_v2, cudaFuncAttributeMaxDynamicSharedMemorySize, smemfc);
    cudaFuncSetAttribute((const void*)dist_v3,  cudaFuncAttributeMaxDynamicSharedMemorySize, smemd);

    prep_kernel<<<64, 256>>>(Wo1, Wo2, proto);
    prep_afrag<<<100, 256>>>(W1, (u32*)af1, 76, 5);
    prep_afrag<<<160, 256>>>(W2, (u32*)af2, 128, 8);
    prep_afrag<<<160, 256>>>(W3, (u32*)af3, 128, 8);

    conv_mma<76, 5>  <<<dim3(32, NB), 256>>>(x,          (const uint4*)af1, b1, (float*)h1, 2048, 1024);
    conv_mma<128, 8> <<<dim3(16, NB), 256>>>((float*)h1, (const uint4*)af2, b2, (float*)h2, 1024, 512);
    conv_mma<128, 8> <<<dim3(8,  NB), 256>>>((float*)h2, (const uint4*)af3, b3, (float*)h3, 512,  256);

    fc_fused_v2<<<dim3(16, NB), 128, smemfc>>>((const float*)h3, (const float*)wo1t, bo1,
                                               (const float*)wo2t, bo2, (float*)f, (float*)fsq);
    dist_v3<<<dim3(16, NB), 128, smemd>>>(proto);
    final_kernel<<<NB, 128>>>(cls, out);
}

// round 16
// speedup vs baseline: 1.6941x; 1.0002x over previous
#include <cuda_runtime.h>
#include <cuda_bf16.h>
#include <math.h>

// ---------------------------------------------------------------------------
// ProtICU R15: convs on warp-level tensor cores (mma.sync m16n8k16 bf16,
// fp32 acc, hi/lo split x3 products). tcgen05 is unavailable (harness PTX
// targets plain sm_103), but mma.sync/ldmatrix are sm_80+ features.
// Conv-as-shifted-GEMM: one 68-row x tile per CTA serves all 5 taps via
// ldmatrix row offset. Weights pre-baked in A-fragment order (LDG.128).
// fc/dist/final: unchanged FFMA2 kernels.
// ---------------------------------------------------------------------------

#define NB 32
typedef unsigned long long u64;
typedef unsigned int u32;

__device__ float g_h1[NB * 1024 * 128];
__device__ float g_h2[NB * 512 * 128];
__device__ float g_h3[NB * 256 * 128];
__device__ float g_f [NB * 256 * 128];
__device__ float g_fsq[NB * 256];
__device__ uint4 g_af1[12800];    // conv1 A-frags: 5 taps x 5 ks x 2 split x 8 mt x 32 lanes
__device__ uint4 g_af2[20480];    // conv2: 5 x 8 x 2 x 8 x 32
__device__ uint4 g_af3[20480];
__device__ float g_wo1t[128 * 128];
__device__ float g_wo2t[128 * 128];
__device__ float g_psq[128];
__device__ float g_minpart[NB * 16 * 128];

__device__ __forceinline__ void ffma2(u64& d, u64 a, u64 b) {
    asm("fma.rn.f32x2 %0, %1, %2, %0;" : "+l"(d) : "l"(a), "l"(b));
}
__device__ __forceinline__ u64 dup2(float v) {
    u64 r;
    asm("mov.b64 %0, {%1, %1};" : "=l"(r) : "f"(v));
    return r;
}
__device__ __forceinline__ u32 s2u32(const void* p) {
    u32 a;
    asm("{ .reg .u64 t; cvta.to.shared.u64 t, %1; cvt.u32.u64 %0, t; }" : "=r"(a) : "l"(p));
    return a;
}
__device__ __forceinline__ void ldmx4(u32* r, u32 addr) {
    asm volatile("ldmatrix.sync.aligned.m8n8.x4.shared.b16 {%0,%1,%2,%3}, [%4];"
                 : "=r"(r[0]), "=r"(r[1]), "=r"(r[2]), "=r"(r[3]) : "r"(addr));
}
__device__ __forceinline__ void mma16816(float* d, const uint4& a, u32 b0, u32 b1) {
    asm volatile(
        "mma.sync.aligned.m16n8k16.row.col.f32.bf16.bf16.f32 "
        "{%0,%1,%2,%3},{%4,%5,%6,%7},{%8,%9},{%0,%1,%2,%3};"
        : "+f"(d[0]), "+f"(d[1]), "+f"(d[2]), "+f"(d[3])
        : "r"(a.x), "r"(a.y), "r"(a.z), "r"(a.w), "r"(b0), "r"(b1));
}

// ---------------------------------------------------------------------------
// prep: 1x1-conv weight transposes + prototype norms.
// ---------------------------------------------------------------------------
__global__ void prep_kernel(const float* __restrict__ Wo1, const float* __restrict__ Wo2,
                            const float* __restrict__ proto) {
    const int stride = gridDim.x * blockDim.x;
    for (int i = blockIdx.x * blockDim.x + threadIdx.x; i < 128 * 128; i += stride) {
        const int o = i & 127, c = i >> 7;
        g_wo1t[i] = Wo1[o * 128 + c];
        g_wo2t[i] = Wo2[o * 128 + c];
        if (i < 128) {
            float s = 0.f;
            for (int d = 0; d < 128; d++) { float v = proto[i * 128 + d]; s = fmaf(v, v, s); }
            g_psq[i] = s;
        }
    }
}

// ---------------------------------------------------------------------------
// prep: bake conv weights into mma A-fragment order.
// af[u32 i]: reg=i&3, lane=(i>>2)&31, mt=(i>>7)&7, split=(i>>10)&1, t=i>>11
// (t = tap*NKS+ks). A frag (m16k16 row-major): m = mt*16 + (lane>>2) +
// 8*(reg&1); k = ks*16 + (lane&3)*2 + 4*(reg&2) + e.  W layout: [O][CIN][5].
// ---------------------------------------------------------------------------
__global__ void prep_afrag(const float* __restrict__ W, u32* __restrict__ af,
                           int CIN, int NKS) {
    const int total = 5 * NKS * 2 * 8 * 128;
    const int stride = gridDim.x * blockDim.x;
    for (int i = blockIdx.x * blockDim.x + threadIdx.x; i < total; i += stride) {
        const int reg = i & 3, lane = (i >> 2) & 31, mt = (i >> 7) & 7;
        const int split = (i >> 10) & 1, t = i >> 11;
        const int tap = t / NKS, ks = t - tap * NKS;
        const int m  = mt * 16 + (lane >> 2) + (reg & 1) * 8;
        const int k0 = ks * 16 + (lane & 3) * 2 + (reg & 2) * 4;
        unsigned short h[2];
        for (int e = 0; e < 2; e++) {
            const int c = k0 + e;
            const float v = (c < CIN) ? W[(m * CIN + c) * 5 + tap] : 0.f;
            __nv_bfloat16 b = __float2bfloat16(v);
            if (split) b = __float2bfloat16(v - __bfloat162float(b));
            memcpy(&h[e], &b, 2);
        }
        af[i] = ((u32)h[1] << 16) | (u32)h[0];
    }
}

// ---------------------------------------------------------------------------
// Tensor-core conv1d(k=5,same)+bias+ReLU+maxpool2.
// 256 threads = 8 warps; warp = (mband = wid&3 : 32 out-ch) x (nhalf = wid>>2
// : 32 prepool positions). CTA tile: 128 ch x 64 prepool (32 pooled).
// x tile: 68 rows x 256B (hi + lo), XOR-swizzled 16B chunks; tap shift is a
// row offset in the ldmatrix address. 24 mma per (tap, kstep) per warp.
// ---------------------------------------------------------------------------
template <int CIN, int NKS>
__global__ void __launch_bounds__(256)
conv_mma(const float* __restrict__ in, const uint4* __restrict__ af,
         const float* __restrict__ bias, float* __restrict__ out,
         int Lin, int Lpool) {
    __shared__ __align__(16) char xs[2 * 68 * 256];
    const u32 XHI = s2u32(xs);
    const u32 XLO = XHI + 68 * 256;

    const int tid  = threadIdx.x;
    const int wid  = tid >> 5;
    const int lane = tid & 31;
    const int mb   = wid & 3;
    const int nh   = wid >> 2;
    const int b    = blockIdx.y;
    const int l0   = blockIdx.x * 64;

    // zero tiles
    for (int i = tid; i < (2 * 68 * 256) / 16; i += 256)
        ((uint4*)xs)[i] = make_uint4(0, 0, 0, 0);
    __syncthreads();

    // fill x tile (hi/lo bf16, swizzled)
    const float* inb = in + (size_t)b * Lin * CIN;
    for (int idx = tid; idx < 68 * CIN; idx += 256) {
        const int r = idx / CIN, c = idx - r * CIN;
        const int gl = l0 - 2 + r;
        const float v = (gl >= 0 && gl < Lin) ? inb[(size_t)gl * CIN + c] : 0.f;
        const __nv_bfloat16 hi = __float2bfloat16(v);
        const __nv_bfloat16 lo = __float2bfloat16(v - __bfloat162float(hi));
        const int addr = r * 256 + (((c >> 3) ^ (r & 7)) << 4) + (c & 7) * 2;
        *(__nv_bfloat16*)(xs + addr)             = hi;
        *(__nv_bfloat16*)(xs + 68 * 256 + addr)  = lo;
    }
    __syncthreads();

    float d[2][4][4];
#pragma unroll
    for (int mt = 0; mt < 2; mt++)
#pragma unroll
        for (int nt = 0; nt < 4; nt++)
#pragma unroll
            for (int e = 0; e < 4; e++) d[mt][nt][e] = 0.f;

    // ldmatrix lane geometry: matrix = lane>>3 (ntl = bit1, khalf = bit0)
    const int prow = nh * 32 + ((lane >> 4) << 3) + (lane & 7);
    const int khb  = (lane >> 3) & 1;

#pragma unroll 1
    for (int tap = 0; tap < 5; tap++) {
#pragma unroll
        for (int ks = 0; ks < NKS; ks++) {
            const int t = tap * NKS + ks;
            const uint4 AH0 = af[((t * 2 + 0) * 8 + mb * 2 + 0) * 32 + lane];
            const uint4 AH1 = af[((t * 2 + 0) * 8 + mb * 2 + 1) * 32 + lane];
            const uint4 AL0 = af[((t * 2 + 1) * 8 + mb * 2 + 0) * 32 + lane];
            const uint4 AL1 = af[((t * 2 + 1) * 8 + mb * 2 + 1) * 32 + lane];

            u32 bh[8], bl[8];
#pragma unroll
            for (int g = 0; g < 2; g++) {
                const int pos   = prow + g * 16 + tap;
                const int chunk = ks * 2 + khb;
                const u32 off = (u32)(pos * 256 + ((chunk ^ (pos & 7)) << 4));
                ldmx4(bh + 4 * g, XHI + off);
                ldmx4(bl + 4 * g, XLO + off);
            }
#pragma unroll
            for (int nt = 0; nt < 4; nt++) {
                mma16816(d[0][nt], AH0, bh[2 * nt], bh[2 * nt + 1]);
                mma16816(d[1][nt], AH1, bh[2 * nt], bh[2 * nt + 1]);
                mma16816(d[0][nt], AH0, bl[2 * nt], bl[2 * nt + 1]);
                mma16816(d[1][nt], AH1, bl[2 * nt], bl[2 * nt + 1]);
                mma16816(d[0][nt], AL0, bh[2 * nt], bh[2 * nt + 1]);
                mma16816(d[1][nt], AL1, bh[2 * nt], bh[2 * nt + 1]);
            }
        }
    }

    // epilogue: bias + relu + maxpool2 (pool pair = d[.][.]{0,1} / {2,3})
    float* outb = out + ((size_t)b * Lpool + blockIdx.x * 32) * 128;
#pragma unroll
    for (int mt = 0; mt < 2; mt++) {
        const int ch0 = mb * 32 + mt * 16 + (lane >> 2);
        const float bv0 = bias[ch0];
        const float bv8 = bias[ch0 + 8];
#pragma unroll
        for (int nt = 0; nt < 4; nt++) {
            const int p = nh * 16 + nt * 4 + (lane & 3);
            const float v0 = fmaxf(fmaxf(d[mt][nt][0], d[mt][nt][1]) + bv0, 0.f);
            const float v1 = fmaxf(fmaxf(d[mt][nt][2], d[mt][nt][3]) + bv8, 0.f);
            outb[(size_t)p * 128 + ch0]     = v0;
            outb[(size_t)p * 128 + ch0 + 8] = v1;
        }
    }
}

// ---------------------------------------------------------------------------
// Fused 1x1 convs (2 layers) + ReLU + fsq. (unchanged from R12/R13)
// ---------------------------------------------------------------------------
__global__ void __launch_bounds__(128)
fc_fused_v2(const float* __restrict__ in, const float* __restrict__ w1t,
            const float* __restrict__ b1, const float* __restrict__ w2t,
            const float* __restrict__ b2, float* __restrict__ f,
            float* __restrict__ fsq) {
    extern __shared__ char smem[];
    float* ws = (float*)smem;
    float* hs = (float*)(smem + 16384);
    float* ms = (float*)(smem + 16384 + 8704);

    const int tid  = threadIdx.x;
    const int op   = tid & 31;
    const int q    = tid >> 5;
    const int r0   = q * 4;
    const int b    = blockIdx.y;
    const int row0 = blockIdx.x * 16;
    const unsigned ws_base = (unsigned)__cvta_generic_to_shared(ws);

    for (int i = tid; i < 512; i += 128) {
        asm volatile("cp.async.ca.shared.global [%0], [%1], 16;"
                     :: "r"(ws_base + i * 16), "l"(w1t + i * 4));
    }
    asm volatile("cp.async.commit_group;" ::: "memory");

    const float* inb = in + ((size_t)b * 256 + row0) * 128;
    for (int i = tid; i < 16 * 128; i += 128) {
        const int r = i >> 7, c = i & 127;
        hs[c * 17 + r] = inb[i];
    }

    u64 accA[4], accB[4];
    {
        const float2 ba = *(const float2*)(b1 + 2 * op);
        const float2 bb = *(const float2*)(b1 + 64 + 2 * op);
        u64 pa, pb;
        asm("mov.b64 %0, {%1,%2};" : "=l"(pa) : "f"(ba.x), "f"(ba.y));
        asm("mov.b64 %0, {%1,%2};" : "=l"(pb) : "f"(bb.x), "f"(bb.y));
#pragma unroll
        for (int j = 0; j < 4; j++) { accA[j] = pa; accB[j] = pb; }
    }

    for (int c0 = 0; c0 < 8; c0++) {
        asm volatile("cp.async.wait_group 0;" ::: "memory");
        __syncthreads();
        if (c0 + 1 < 8) {
            const float*   src = w1t + (c0 + 1) * 2048;
            const unsigned dst = ws_base + ((c0 + 1) & 1) * 8192;
            for (int i = tid; i < 512; i += 128) {
                asm volatile("cp.async.ca.shared.global [%0], [%1], 16;"
                             :: "r"(dst + i * 16), "l"(src + i * 4));
            }
            asm volatile("cp.async.commit_group;" ::: "memory");
        }
        const float* wbuf = ws + (c0 & 1) * 2048;
#pragma unroll
        for (int cc = 0; cc < 16; cc++) {
            const u64 wa = *(const u64*)(wbuf + cc * 128 + 2 * op);
            const u64 wb = *(const u64*)(wbuf + cc * 128 + 64 + 2 * op);
            const float* xb = hs + (c0 * 16 + cc) * 17 + r0;
#pragma unroll
            for (int j = 0; j < 4; j++) {
                const u64 x = dup2(xb[j]);
                ffma2(accA[j], wa, x);
                ffma2(accB[j], wb, x);
            }
        }
    }

    __syncthreads();
    for (int i = tid; i < 512; i += 128) {
        asm volatile("cp.async.ca.shared.global [%0], [%1], 16;"
                     :: "r"(ws_base + i * 16), "l"(w2t + i * 4));
    }
    asm volatile("cp.async.commit_group;" ::: "memory");

#pragma unroll
    for (int j = 0; j < 4; j++) {
        float2 a = *(const float2*)&accA[j];
        float2 c = *(const float2*)&accB[j];
        const int r = r0 + j;
        ms[(2 * op)      * 17 + r] = fmaxf(a.x, 0.f);
        ms[(2 * op + 1)  * 17 + r] = fmaxf(a.y, 0.f);
        ms[(64 + 2 * op) * 17 + r] = fmaxf(c.x, 0.f);
        ms[(65 + 2 * op) * 17 + r] = fmaxf(c.y, 0.f);
    }

    {
        const float2 ba = *(const float2*)(b2 + 2 * op);
        const float2 bb = *(const float2*)(b2 + 64 + 2 * op);
        u64 pa, pb;
        asm("mov.b64 %0, {%1,%2};" : "=l"(pa) : "f"(ba.x), "f"(ba.y));
        asm("mov.b64 %0, {%1,%2};" : "=l"(pb) : "f"(bb.x), "f"(bb.y));
#pragma unroll
        for (int j = 0; j < 4; j++) { accA[j] = pa; accB[j] = pb; }
    }

    for (int c0 = 0; c0 < 8; c0++) {
        asm volatile("cp.async.wait_group 0;" ::: "memory");
        __syncthreads();
        if (c0 + 1 < 8) {
            const float*   src = w2t + (c0 + 1) * 2048;
            const unsigned dst = ws_base + ((c0 + 1) & 1) * 8192;
            for (int i = tid; i < 512; i += 128) {
                asm volatile("cp.async.ca.shared.global [%0], [%1], 16;"
                             :: "r"(dst + i * 16), "l"(src + i * 4));
            }
            asm volatile("cp.async.commit_group;" ::: "memory");
        }
        const float* wbuf = ws + (c0 & 1) * 2048;
#pragma unroll
        for (int cc = 0; cc < 16; cc++) {
            const u64 wa = *(const u64*)(wbuf + cc * 128 + 2 * op);
            const u64 wb = *(const u64*)(wbuf + cc * 128 + 64 + 2 * op);
            const float* xb = ms + (c0 * 16 + cc) * 17 + r0;
#pragma unroll
            for (int j = 0; j < 4; j++) {
                const u64 x = dup2(xb[j]);
                ffma2(accA[j], wa, x);
                ffma2(accB[j], wb, x);
            }
        }
    }

    float* fb = f + ((size_t)b * 256 + row0 + r0) * 128;
#pragma unroll
    for (int j = 0; j < 4; j++) {
        float2 a = *(const float2*)&accA[j];
        float2 c = *(const float2*)&accB[j];
        a.x = fmaxf(a.x, 0.f); a.y = fmaxf(a.y, 0.f);
        c.x = fmaxf(c.x, 0.f); c.y = fmaxf(c.y, 0.f);
        *(float2*)(fb + (size_t)j * 128 + 2 * op)      = a;
        *(float2*)(fb + (size_t)j * 128 + 64 + 2 * op) = c;
        float s = a.x * a.x + a.y * a.y + c.x * c.x + c.y * c.y;
#pragma unroll
        for (int off = 16; off; off >>= 1) s += __shfl_down_sync(0xffffffffu, s, off);
        if (op == 0) fsq[(size_t)b * 256 + row0 + r0 + j] = s;
    }
}

// ---------------------------------------------------------------------------
// Prototype L2 distances, 16-row chunks. (unchanged)
// ---------------------------------------------------------------------------
__global__ void __launch_bounds__(128)
dist_v3(const float* __restrict__ proto) {
    extern __shared__ char smem[];
    float* protoS = (float*)smem;
    float* fs     = (float*)(smem + 66560);

    const int b = blockIdx.y, chunk = blockIdx.x;
    const int p = threadIdx.x;

    for (int i = p; i < 128 * 128; i += 128) {
        const int pp = i >> 7, d = i & 127;
        protoS[pp * 130 + d] = proto[i];
    }
    const float psqv = g_psq[p];
    const float* fb = g_f   + ((size_t)(b * 256 + chunk * 16)) * 128;
    const float* fq = g_fsq + b * 256 + chunk * 16;
    float best = 3.4e38f;

    for (int l0 = 0; l0 < 16; l0 += 8) {
        __syncthreads();
        for (int i = p; i < 1024; i += 128) fs[i] = fb[(size_t)l0 * 128 + i];
        __syncthreads();

        u64 acc2[8];
#pragma unroll
        for (int r = 0; r < 8; r++) acc2[r] = 0ull;
#pragma unroll
        for (int dc = 0; dc < 4; dc++) {
            u64 ptr_[16];
#pragma unroll
            for (int i = 0; i < 16; i++)
                ptr_[i] = *(const u64*)(protoS + p * 130 + dc * 32 + 2 * i);
#pragma unroll
            for (int r = 0; r < 8; r++) {
                const float* fr = fs + r * 128 + dc * 32;
#pragma unroll
                for (int i = 0; i < 16; i++)
                    ffma2(acc2[r], ptr_[i], *(const u64*)(fr + 2 * i));
            }
        }
#pragma unroll
        for (int r = 0; r < 8; r++) {
            const float2 a = *(const float2*)&acc2[r];
            const float dot = a.x + a.y;
            const float d2 = fq[l0 + r] - 2.f * dot + psqv;
            best = fminf(best, d2);
        }
    }
    g_minpart[(b * 16 + chunk) * 128 + p] = best;
}

// ---------------------------------------------------------------------------
// Final head.  d_out[0:64] = out(32,2); d_out[64:4160] = min_dis(32,128).
// ---------------------------------------------------------------------------
__global__ void final_kernel(const int* __restrict__ classes, float* __restrict__ outp) {
    const int b = blockIdx.x, p = threadIdx.x;
    float m = 3.4e38f;
#pragma unroll
    for (int c = 0; c < 16; c++)
        m = fminf(m, g_minpart[(b * 16 + c) * 128 + p]);
    const float dis = sqrtf(fmaxf(m, 1e-12f));
    const float sim = logf((dis + 1.f) / (dis + 1e-4f));
    outp[64 + b * 128 + p] = dis;

    __shared__ float ss[128];
    ss[p] = sim;
    __syncthreads();
    if (p < 2) {
        float s = 0.f;
        for (int q = 0; q < 128; q++)
            s += ss[q] * ((classes[q] == p) ? 1.f : -0.5f);
        outp[b * 2 + p] = 1.f / (1.f + expf(-s));
    }
}

// ---------------------------------------------------------------------------
extern "C" void kernel_launch(void* const* d_in, const int* in_sizes, int n_in,
                              void* d_out, int out_size) {
    const float* x     = (const float*)d_in[0];
    const float* W1    = (const float*)d_in[1];
    const float* b1    = (const float*)d_in[2];
    const float* W2    = (const float*)d_in[3];
    const float* b2    = (const float*)d_in[4];
    const float* W3    = (const float*)d_in[5];
    const float* b3    = (const float*)d_in[6];
    const float* Wo1   = (const float*)d_in[7];
    const float* bo1   = (const float*)d_in[8];
    const float* Wo2   = (const float*)d_in[9];
    const float* bo2   = (const float*)d_in[10];
    const float* proto = (const float*)d_in[11];
    const int*   cls   = (const int*)d_in[12];
    float* out = (float*)d_out;
    (void)in_sizes; (void)n_in; (void)out_size;

    void *h1, *h2, *h3, *f, *fsq, *af1, *af2, *af3, *wo1t, *wo2t;
    cudaGetSymbolAddress(&h1, g_h1);
    cudaGetSymbolAddress(&h2, g_h2);
    cudaGetSymbolAddress(&h3, g_h3);
    cudaGetSymbolAddress(&f,  g_f);
    cudaGetSymbolAddress(&fsq, g_fsq);
    cudaGetSymbolAddress(&af1, g_af1);
    cudaGetSymbolAddress(&af2, g_af2);
    cudaGetSymbolAddress(&af3, g_af3);
    cudaGetSymbolAddress(&wo1t, g_wo1t);
    cudaGetSymbolAddress(&wo2t, g_wo2t);

    const int smemfc = 16384 + 2 * 8704;              // 33792
    const int smemd  = 66560 + 4096;                  // 70656
    cudaFuncSetAttribute((const void*)fc_fused_v2, cudaFuncAttributeMaxDynamicSharedMemorySize, smemfc);
    cudaFuncSetAttribute((const void*)dist_v3,  cudaFuncAttributeMaxDynamicSharedMemorySize, smemd);

    prep_kernel<<<64, 256>>>(Wo1, Wo2, proto);
    prep_afrag<<<100, 256>>>(W1, (u32*)af1, 76, 5);
    prep_afrag<<<160, 256>>>(W2, (u32*)af2, 128, 8);
    prep_afrag<<<160, 256>>>(W3, (u32*)af3, 128, 8);

    conv_mma<76, 5>  <<<dim3(32, NB), 256>>>(x,          (const uint4*)af1, b1, (float*)h1, 2048, 1024);
    conv_mma<128, 8> <<<dim3(16, NB), 256>>>((float*)h1, (const uint4*)af2, b2, (float*)h2, 1024, 512);
    conv_mma<128, 8> <<<dim3(8,  NB), 256>>>((float*)h2, (const uint4*)af3, b3, (float*)h3, 512,  256);

    fc_fused_v2<<<dim3(16, NB), 128, smemfc>>>((const float*)h3, (const float*)wo1t, bo1,
                                               (const float*)wo2t, bo2, (float*)f, (float*)fsq);
    dist_v3<<<dim3(16, NB), 128, smemd>>>(proto);
    final_kernel<<<NB, 128>>>(cls, out);
}